// round 9
// baseline (speedup 1.0000x reference)
#include <cuda_runtime.h>
#include <cstdint>

#define N1 16384
#define N2 16384
#define GRID 128
#define NCELL (GRID * GRID)
#define RLO (-6.0f)
#define RANGE 12.0f
#define CELLW (RANGE / (float)GRID)      // 0.09375, exact in fp32
#define INVCELL ((float)GRID / RANGE)
#define BLOCKS 256
#define TPB 256
#define GSZ 4                            // lanes per query
#define CPB (NCELL / BLOCKS)             // 64 cells per block
#define FINF __uint_as_float(0x7f800000u)

// Cell counts: zero at kernel entry (static zero init; re-zeroed in-kernel
// after the scan consumes them -> replay invariant).
__device__ int g_cnt[NCELL];
// After scan: exclusive prefix. After scatter: inclusive end per cell.
// start(c) = (c>0) ? g_ofs[c-1] : 0.  Rewritten fresh every launch.
__device__ int g_ofs[NCELL];
__device__ int g_btot[BLOCKS];
__device__ int g_boff[BLOCKS];
__device__ float2 g_spts[N2];
__device__ float g_bsum[BLOCKS];
// Monotonic spin-barrier counter (phase-free; wraps after ~2.8M replays).
__device__ unsigned int g_bar_cnt = 0;

__device__ __forceinline__ int clampi(int v, int lo, int hi) {
    return max(lo, min(hi, v));
}

__device__ __forceinline__ int cell_of(float x, float y) {
    int ix = clampi((int)((x - RLO) * INVCELL), 0, GRID - 1);
    int iy = clampi((int)((y - RLO) * INVCELL), 0, GRID - 1);
    return iy * GRID + ix;
}

// Grid-wide barrier: all BLOCKS blocks are co-resident (grid 256 <= 4/SM * 152).
__device__ __forceinline__ void grid_bar() {
    __syncthreads();
    if (threadIdx.x == 0) {
        __threadfence();
        unsigned int my = atomicAdd(&g_bar_cnt, 1u) + 1u;
        unsigned int target = ((my + BLOCKS - 1u) / BLOCKS) * BLOCKS;
        while (*((volatile unsigned int*)&g_bar_cnt) < target) {
            __nanosleep(32);
        }
        __threadfence();
    }
    __syncthreads();
}

// Scan points [s,e) with this lane's stride-GSZ subset.
__device__ __forceinline__ void scan_pts(int s, int e, int sub,
                                         float qx, float qy, float& m) {
    for (int i = s + sub; i < e; i += GSZ) {
        float2 p = g_spts[i];
        float dx = qx - p.x;
        float dy = qy - p.y;
        m = fminf(m, fmaf(dx, dx, dy * dy));
    }
}

__device__ __forceinline__ void scan_cells(int c0, int c1, int sub,
                                           float qx, float qy, float& m) {
    int s = (c0 > 0) ? g_ofs[c0 - 1] : 0;
    scan_pts(s, g_ofs[c1], sub, qx, qy, m);
}

__global__ __launch_bounds__(TPB, 4)
void fused_kernel(const float2* __restrict__ pos1,
                  const float2* __restrict__ pos2,
                  float* __restrict__ out) {
    __shared__ int sscan[TPB];
    __shared__ float red[TPB];

    const int tid  = threadIdx.x;
    const int b    = blockIdx.x;
    const int gtid = b * TPB + tid;

    // ── Phase A: count ───────────────────────────────────────────────────────
    if (gtid < N2) {
        float2 p = pos2[gtid];
        atomicAdd(&g_cnt[cell_of(p.x, p.y)], 1);
    }
    grid_bar();

    // ── Phase B1: block-local inclusive scan of this block's 64 cells ────────
    const int cbase = b * CPB;
    int myc = (tid < CPB) ? g_cnt[cbase + tid] : 0;
    sscan[tid] = (tid < CPB) ? myc : 0;
    __syncthreads();
    for (int off = 1; off < CPB; off <<= 1) {
        int v = (tid >= off && tid < CPB) ? sscan[tid - off] : 0;
        __syncthreads();
        if (tid < CPB) sscan[tid] += v;
        __syncthreads();
    }
    int lexcl = (tid < CPB) ? (sscan[tid] - myc) : 0;
    if (tid == CPB - 1) g_btot[b] = sscan[CPB - 1];
    grid_bar();

    // ── Phase B2: block 0 scans the 256 block totals ─────────────────────────
    if (b == 0) {
        int v = g_btot[tid];
        sscan[tid] = v;
        __syncthreads();
        for (int off = 1; off < TPB; off <<= 1) {
            int u = (tid >= off) ? sscan[tid - off] : 0;
            __syncthreads();
            sscan[tid] += u;
            __syncthreads();
        }
        g_boff[tid] = sscan[tid] - v;   // exclusive block offset
    }
    grid_bar();

    // ── Phase B3: write exclusive prefix, restore zero invariant ─────────────
    if (tid < CPB) {
        g_ofs[cbase + tid] = g_boff[b] + lexcl;
        g_cnt[cbase + tid] = 0;
    }
    grid_bar();

    // ── Phase C: scatter (atomicAdd turns g_ofs into inclusive ends) ─────────
    if (gtid < N2) {
        float2 p = pos2[gtid];
        int c = cell_of(p.x, p.y);
        int pos = atomicAdd(&g_ofs[c], 1);
        g_spts[pos] = p;
    }
    grid_bar();

    // ── Phase D: query, GSZ lanes per pos1 point ─────────────────────────────
    const int q   = gtid >> 2;
    const int sub = gtid & (GSZ - 1);

    float2 qp = pos1[q];
    int ix = clampi((int)((qp.x - RLO) * INVCELL), 0, GRID - 1);
    int iy = clampi((int)((qp.y - RLO) * INVCELL), 0, GRID - 1);

    float m = FINF;

    // Fast path: 3x3 neighborhood; 6 range offsets loaded up front (batched).
    int x0 = max(ix - 1, 0), x1 = min(ix + 1, GRID - 1);
    int y0 = max(iy - 1, 0), y1 = min(iy + 1, GRID - 1);
    int nrows = y1 - y0 + 1;
    int rs[3], re[3];
#pragma unroll
    for (int k = 0; k < 3; k++) {
        int yy = min(y0 + k, y1);
        int c0 = yy * GRID + x0;
        rs[k] = (c0 > 0) ? g_ofs[c0 - 1] : 0;
        re[k] = g_ofs[yy * GRID + x1];
    }
#pragma unroll
    for (int k = 0; k < 3; k++) {
        if (k < nrows) scan_pts(rs[k], re[k], sub, qp.x, qp.y, m);
    }

    // Ring expansion r >= 2 with per-lane min. A lane stops only when
    // (r-1)*CELLW bounds all points in rings >= r above its own m, so any
    // point this lane skips cannot beat the group-combined min. Almost always
    // breaks immediately (typical m ~ 1.6e-4 << CELLW^2 ~ 8.8e-3).
    for (int r = 2; r < GRID; r++) {
        float lb = (float)(r - 1) * CELLW;
        if (lb * lb >= m) break;
        int xa = max(ix - r, 0), xb = min(ix + r, GRID - 1);
        if (iy - r >= 0)
            scan_cells((iy - r) * GRID + xa, (iy - r) * GRID + xb, sub, qp.x, qp.y, m);
        if (iy + r <= GRID - 1)
            scan_cells((iy + r) * GRID + xa, (iy + r) * GRID + xb, sub, qp.x, qp.y, m);
        int ya = max(iy - r + 1, 0), yb = min(iy + r - 1, GRID - 1);
        if (ix - r >= 0)
            for (int yy = ya; yy <= yb; yy++)
                scan_cells(yy * GRID + (ix - r), yy * GRID + (ix - r), sub, qp.x, qp.y, m);
        if (ix + r <= GRID - 1)
            for (int yy = ya; yy <= yb; yy++)
                scan_cells(yy * GRID + (ix + r), yy * GRID + (ix + r), sub, qp.x, qp.y, m);
    }

    // Combine the 4 lanes' mins (fmin is exactly associative -> deterministic).
    m = fminf(m, __shfl_xor_sync(0xffffffffu, m, 1));
    m = fminf(m, __shfl_xor_sync(0xffffffffu, m, 2));

    red[tid] = (sub == 0) ? sqrtf(m) : 0.0f;
    __syncthreads();
    for (int w = TPB / 2; w > 0; w >>= 1) {
        if (tid < w) red[tid] += red[tid + w];
        __syncthreads();
    }
    if (tid == 0) g_bsum[b] = red[0];
    grid_bar();

    // ── Phase E: final mean (block 0) ────────────────────────────────────────
    if (b == 0) {
        red[tid] = g_bsum[tid];
        __syncthreads();
        for (int w = TPB / 2; w > 0; w >>= 1) {
            if (tid < w) red[tid] += red[tid + w];
            __syncthreads();
        }
        if (tid == 0) out[0] = red[0] * (1.0f / (float)N1);
    }
}

extern "C" void kernel_launch(void* const* d_in, const int* in_sizes, int n_in,
                              void* d_out, int out_size) {
    const float2* pos1 = (const float2*)d_in[0];
    const float2* pos2 = (const float2*)d_in[1];
    float* out = (float*)d_out;

    fused_kernel<<<BLOCKS, TPB>>>(pos1, pos2, out);
}

// round 12
// speedup vs baseline: 1.0455x; 1.0455x over previous
#include <cuda_runtime.h>
#include <cstdint>

#define N1 16384
#define N2 16384
#define GRID 128
#define NCELL (GRID * GRID)
#define RLO (-6.0f)
#define RANGE 12.0f
#define CELLW (RANGE / (float)GRID)      // 0.09375, exact in fp32
#define INVCELL ((float)GRID / RANGE)
#define QBLOCKS 512
#define QTHREADS 128
#define GSZ 4                            // lanes per query
#define FINF __uint_as_float(0x7f800000u)

// Cell counts: zero at kernel entry (static zero init; scan_kernel re-zeroes
// after consuming -> replay invariant).
__device__ int g_cnt[NCELL];
// After scan: exclusive prefix. After scatter: inclusive end per cell.
// start(c) = (c>0) ? g_ofs[c-1] : 0.  Rewritten fresh every launch.
__device__ int g_ofs[NCELL];
__device__ float2 g_spts[N2];
__device__ float g_bsum[QBLOCKS];
__device__ unsigned int g_done = 0;

__device__ __forceinline__ int clampi(int v, int lo, int hi) {
    return max(lo, min(hi, v));
}

__device__ __forceinline__ int cell_of(float x, float y) {
    int ix = clampi((int)((x - RLO) * INVCELL), 0, GRID - 1);
    int iy = clampi((int)((y - RLO) * INVCELL), 0, GRID - 1);
    return iy * GRID + ix;
}

// ── Kernel 1: count ──────────────────────────────────────────────────────────
__global__ __launch_bounds__(256)
void count_kernel(const float2* __restrict__ pos2) {
    int i = blockIdx.x * 256 + threadIdx.x;
    float2 p = pos2[i];
    atomicAdd(&g_cnt[cell_of(p.x, p.y)], 1);
}

// ── Kernel 2: exclusive scan over 16384 cells (1 block, int4-vectorized) ─────
__global__ __launch_bounds__(1024)
void scan_kernel() {
    __shared__ int sc[1024];
    const int t = threadIdx.x;
    const int4* cv = (const int4*)&g_cnt[t * 16];
    int4 c[4];
    int loc[16];
    int s = 0;
#pragma unroll
    for (int k = 0; k < 4; k++) c[k] = cv[k];
#pragma unroll
    for (int k = 0; k < 4; k++) {
        loc[4 * k + 0] = s; s += c[k].x;
        loc[4 * k + 1] = s; s += c[k].y;
        loc[4 * k + 2] = s; s += c[k].z;
        loc[4 * k + 3] = s; s += c[k].w;
    }
    sc[t] = s;
    __syncthreads();
    for (int off = 1; off < 1024; off <<= 1) {
        int v = (t >= off) ? sc[t - off] : 0;
        __syncthreads();
        sc[t] += v;
        __syncthreads();
    }
    int excl = sc[t] - s;
    int4* ov = (int4*)&g_ofs[t * 16];
    int4* zv = (int4*)&g_cnt[t * 16];
    const int4 zero = make_int4(0, 0, 0, 0);
#pragma unroll
    for (int k = 0; k < 4; k++) {
        ov[k] = make_int4(excl + loc[4 * k + 0], excl + loc[4 * k + 1],
                          excl + loc[4 * k + 2], excl + loc[4 * k + 3]);
        zv[k] = zero;                    // restore zero invariant for replay
    }
}

// ── Kernel 3: scatter (atomicAdd turns g_ofs into inclusive ends) ────────────
__global__ __launch_bounds__(256)
void scatter_kernel(const float2* __restrict__ pos2) {
    int i = blockIdx.x * 256 + threadIdx.x;
    float2 p = pos2[i];
    int c = cell_of(p.x, p.y);
    int pos = atomicAdd(&g_ofs[c], 1);
    g_spts[pos] = p;
}

// Scan points [s,e) with this lane's stride-GSZ subset. No collective ops.
__device__ __forceinline__ void scan_pts(int s, int e, int sub,
                                         float qx, float qy, float& m) {
    for (int i = s + sub; i < e; i += GSZ) {
        float2 p = g_spts[i];
        float dx = qx - p.x;
        float dy = qy - p.y;
        m = fminf(m, fmaf(dx, dx, dy * dy));
    }
}

__device__ __forceinline__ void scan_cells(int c0, int c1, int sub,
                                           float qx, float qy, float& m) {
    int s = (c0 > 0) ? g_ofs[c0 - 1] : 0;
    scan_pts(s, g_ofs[c1], sub, qx, qy, m);
}

// Min across the 4 lanes of each group. Must be executed by ALL 32 lanes of
// the warp (full mask) — call sites are unconditional.
__device__ __forceinline__ float lane_combine(float m) {
    m = fminf(m, __shfl_xor_sync(0xffffffffu, m, 1));
    m = fminf(m, __shfl_xor_sync(0xffffffffu, m, 2));
    return m;
}

// ── Kernel 4: query, GSZ lanes per pos1 point + fused mean ───────────────────
__global__ __launch_bounds__(QTHREADS)
void query_kernel(const float2* __restrict__ pos1, float* __restrict__ out) {
    __shared__ float red[QTHREADS];
    __shared__ unsigned int s_last;
    const int tid  = threadIdx.x;
    const int gtid = blockIdx.x * QTHREADS + tid;
    const int q    = gtid >> 2;
    const int sub  = gtid & (GSZ - 1);

    float2 qp = pos1[q];
    int ix = clampi((int)((qp.x - RLO) * INVCELL), 0, GRID - 1);
    int iy = clampi((int)((qp.y - RLO) * INVCELL), 0, GRID - 1);

    float m = FINF;

    // Fast path: 3x3 neighborhood; 6 range offsets loaded up front (batched).
    int x0 = max(ix - 1, 0), x1 = min(ix + 1, GRID - 1);
    int y0 = max(iy - 1, 0), y1 = min(iy + 1, GRID - 1);
    int nrows = y1 - y0 + 1;
    int rs[3], re[3];
#pragma unroll
    for (int k = 0; k < 3; k++) {
        int yy = min(y0 + k, y1);
        int c0 = yy * GRID + x0;
        rs[k] = (c0 > 0) ? g_ofs[c0 - 1] : 0;
        re[k] = g_ofs[yy * GRID + x1];
    }
#pragma unroll
    for (int k = 0; k < 3; k++) {
        if (k < nrows) scan_pts(rs[k], re[k], sub, qp.x, qp.y, m);
    }

    m = lane_combine(m);   // unconditional: all 32 lanes participate

    // Exact bound: distance from q to the scanned-rect boundary (border -> inf).
    float bx0 = (x0 == 0)        ? FINF : qp.x - (RLO + (float)x0 * CELLW);
    float bx1 = (x1 == GRID - 1) ? FINF : (RLO + (float)(x1 + 1) * CELLW) - qp.x;
    float by0 = (y0 == 0)        ? FINF : qp.y - (RLO + (float)y0 * CELLW);
    float by1 = (y1 == GRID - 1) ? FINF : (RLO + (float)(y1 + 1) * CELLW) - qp.y;
    float b = fminf(fminf(bx0, bx1), fminf(by0, by1));

    // Rare fallback: ring expansion r >= 2 with per-lane min seeded by the
    // combined m. Contains NO warp-collective ops (plain loads only), so
    // group-level divergence is safe. A lane stops only when (r-1)*CELLW
    // exceeds its OWN min (>= group min), so skipped points cannot beat the
    // final combined result.
    if (b * b < m) {
        for (int r = 2; r < GRID; r++) {
            float lb = (float)(r - 1) * CELLW;
            if (lb * lb >= m) break;
            int xa = max(ix - r, 0), xb = min(ix + r, GRID - 1);
            if (iy - r >= 0)
                scan_cells((iy - r) * GRID + xa, (iy - r) * GRID + xb, sub, qp.x, qp.y, m);
            if (iy + r <= GRID - 1)
                scan_cells((iy + r) * GRID + xa, (iy + r) * GRID + xb, sub, qp.x, qp.y, m);
            int ya = max(iy - r + 1, 0), yb = min(iy + r - 1, GRID - 1);
            if (ix - r >= 0)
                for (int yy = ya; yy <= yb; yy++)
                    scan_cells(yy * GRID + (ix - r), yy * GRID + (ix - r), sub, qp.x, qp.y, m);
            if (ix + r <= GRID - 1)
                for (int yy = ya; yy <= yb; yy++)
                    scan_cells(yy * GRID + (ix + r), yy * GRID + (ix + r), sub, qp.x, qp.y, m);
        }
    }
    m = lane_combine(m);   // unconditional: all 32 lanes participate

    red[tid] = (sub == 0) ? sqrtf(m) : 0.0f;
    __syncthreads();
    for (int w = QTHREADS / 2; w > 0; w >>= 1) {
        if (tid < w) red[tid] += red[tid + w];
        __syncthreads();
    }
    if (tid == 0) g_bsum[blockIdx.x] = red[0];

    // Done-counter tail: last block computes the mean (fixed order -> determ.)
    __threadfence();
    __syncthreads();
    if (tid == 0) {
        unsigned int prev = atomicAdd(&g_done, 1u);
        s_last = (prev == (unsigned int)(QBLOCKS - 1)) ? 1u : 0u;
    }
    __syncthreads();
    if (s_last) {
        __threadfence();
        float s = 0.0f;
#pragma unroll
        for (int k = 0; k < QBLOCKS / QTHREADS; k++) {
            s += __ldcg(&g_bsum[tid + k * QTHREADS]);
        }
        red[tid] = s;
        __syncthreads();
        for (int w = QTHREADS / 2; w > 0; w >>= 1) {
            if (tid < w) red[tid] += red[tid + w];
            __syncthreads();
        }
        if (tid == 0) {
            out[0] = red[0] * (1.0f / (float)N1);
            g_done = 0;   // reset for next replay
        }
    }
}

extern "C" void kernel_launch(void* const* d_in, const int* in_sizes, int n_in,
                              void* d_out, int out_size) {
    const float2* pos1 = (const float2*)d_in[0];
    const float2* pos2 = (const float2*)d_in[1];
    float* out = (float*)d_out;

    count_kernel<<<N2 / 256, 256>>>(pos2);
    scan_kernel<<<1, 1024>>>();
    scatter_kernel<<<N2 / 256, 256>>>(pos2);
    query_kernel<<<QBLOCKS, QTHREADS>>>(pos1, out);
}

// round 13
// speedup vs baseline: 2.9104x; 2.7837x over previous
#include <cuda_runtime.h>
#include <cstdint>

#define N1 16384
#define N2 16384
#define GRID 128
#define NCELL (GRID * GRID)
#define RLO (-6.0f)
#define RANGE 12.0f
#define CELLW (RANGE / (float)GRID)      // 0.09375, exact in fp32
#define INVCELL ((float)GRID / RANGE)
#define QBLOCKS 512
#define QTHREADS 128
#define GSZ 4                            // lanes per query
#define FINF __uint_as_float(0x7f800000u)

// Cell counts: zero at kernel entry (static zero init; scan_kernel re-zeroes
// after consuming -> replay invariant).
__device__ int g_cnt[NCELL];
// After scan: exclusive prefix. After scatter: inclusive end per cell.
// start(c) = (c>0) ? g_ofs[c-1] : 0.  Rewritten fresh every launch.
__device__ int g_ofs[NCELL];
__device__ float2 g_spts[N2];
__device__ float g_bsum[QBLOCKS];
__device__ unsigned int g_done = 0;

__device__ __forceinline__ int clampi(int v, int lo, int hi) {
    return max(lo, min(hi, v));
}

__device__ __forceinline__ int cell_of(float x, float y) {
    int ix = clampi((int)((x - RLO) * INVCELL), 0, GRID - 1);
    int iy = clampi((int)((y - RLO) * INVCELL), 0, GRID - 1);
    return iy * GRID + ix;
}

// ── Kernel 1: count ──────────────────────────────────────────────────────────
__global__ __launch_bounds__(256)
void count_kernel(const float2* __restrict__ pos2) {
    int i = blockIdx.x * 256 + threadIdx.x;
    float2 p = pos2[i];
    atomicAdd(&g_cnt[cell_of(p.x, p.y)], 1);
}

// ── Kernel 2: exclusive scan over 16384 cells (1 block, int4-vectorized) ─────
__global__ __launch_bounds__(1024)
void scan_kernel() {
    __shared__ int sc[1024];
    const int t = threadIdx.x;
    const int4* cv = (const int4*)&g_cnt[t * 16];
    int4 c[4];
    int loc[16];
    int s = 0;
#pragma unroll
    for (int k = 0; k < 4; k++) c[k] = cv[k];
#pragma unroll
    for (int k = 0; k < 4; k++) {
        loc[4 * k + 0] = s; s += c[k].x;
        loc[4 * k + 1] = s; s += c[k].y;
        loc[4 * k + 2] = s; s += c[k].z;
        loc[4 * k + 3] = s; s += c[k].w;
    }
    sc[t] = s;
    __syncthreads();
    for (int off = 1; off < 1024; off <<= 1) {
        int v = (t >= off) ? sc[t - off] : 0;
        __syncthreads();
        sc[t] += v;
        __syncthreads();
    }
    int excl = sc[t] - s;
    int4* ov = (int4*)&g_ofs[t * 16];
    int4* zv = (int4*)&g_cnt[t * 16];
    const int4 zero = make_int4(0, 0, 0, 0);
#pragma unroll
    for (int k = 0; k < 4; k++) {
        ov[k] = make_int4(excl + loc[4 * k + 0], excl + loc[4 * k + 1],
                          excl + loc[4 * k + 2], excl + loc[4 * k + 3]);
        zv[k] = zero;                    // restore zero invariant for replay
    }
}

// ── Kernel 3: scatter (atomicAdd turns g_ofs into inclusive ends) ────────────
__global__ __launch_bounds__(256)
void scatter_kernel(const float2* __restrict__ pos2) {
    int i = blockIdx.x * 256 + threadIdx.x;
    float2 p = pos2[i];
    int c = cell_of(p.x, p.y);
    int pos = atomicAdd(&g_ofs[c], 1);
    g_spts[pos] = p;
}

// Scan points [s,e) with this lane's stride-GSZ subset. No collective ops.
__device__ __forceinline__ void scan_pts(int s, int e, int sub,
                                         float qx, float qy, float& m) {
    for (int i = s + sub; i < e; i += GSZ) {
        float2 p = g_spts[i];
        float dx = qx - p.x;
        float dy = qy - p.y;
        m = fminf(m, fmaf(dx, dx, dy * dy));
    }
}

__device__ __forceinline__ void scan_cells(int c0, int c1, int sub,
                                           float qx, float qy, float& m) {
    int s = (c0 > 0) ? g_ofs[c0 - 1] : 0;
    scan_pts(s, g_ofs[c1], sub, qx, qy, m);
}

// Full-warp variant: all 32 lanes execute (call sites unconditional).
__device__ __forceinline__ float lane_combine(float m) {
    m = fminf(m, __shfl_xor_sync(0xffffffffu, m, 1));
    m = fminf(m, __shfl_xor_sync(0xffffffffu, m, 2));
    return m;
}

// Group-masked variant: legal inside a branch that is UNIFORM within the
// 4-lane group (all lanes named by gmask execute the same call).
__device__ __forceinline__ float group_combine(float m, unsigned int gmask) {
    m = fminf(m, __shfl_xor_sync(gmask, m, 1));
    m = fminf(m, __shfl_xor_sync(gmask, m, 2));
    return m;
}

// ── Kernel 4: query, GSZ lanes per pos1 point + fused mean ───────────────────
__global__ __launch_bounds__(QTHREADS)
void query_kernel(const float2* __restrict__ pos1, float* __restrict__ out) {
    __shared__ float red[QTHREADS];
    __shared__ unsigned int s_last;
    const int tid  = threadIdx.x;
    const int gtid = blockIdx.x * QTHREADS + tid;
    const int q    = gtid >> 2;
    const int sub  = gtid & (GSZ - 1);
    const unsigned int gmask = 0xFu << (tid & 28);   // this group's 4 lanes

    float2 qp = pos1[q];
    int ix = clampi((int)((qp.x - RLO) * INVCELL), 0, GRID - 1);
    int iy = clampi((int)((qp.y - RLO) * INVCELL), 0, GRID - 1);

    float m = FINF;

    // Fast path: 3x3 neighborhood; 6 range offsets loaded up front (batched).
    int x0 = max(ix - 1, 0), x1 = min(ix + 1, GRID - 1);
    int y0 = max(iy - 1, 0), y1 = min(iy + 1, GRID - 1);
    int nrows = y1 - y0 + 1;
    int rs[3], re[3];
#pragma unroll
    for (int k = 0; k < 3; k++) {
        int yy = min(y0 + k, y1);
        int c0 = yy * GRID + x0;
        rs[k] = (c0 > 0) ? g_ofs[c0 - 1] : 0;
        re[k] = g_ofs[yy * GRID + x1];
    }
#pragma unroll
    for (int k = 0; k < 3; k++) {
        if (k < nrows) scan_pts(rs[k], re[k], sub, qp.x, qp.y, m);
    }

    m = lane_combine(m);   // unconditional: all 32 lanes participate

    // Exact bound: distance from q to the scanned-rect boundary (border -> inf).
    float bx0 = (x0 == 0)        ? FINF : qp.x - (RLO + (float)x0 * CELLW);
    float bx1 = (x1 == GRID - 1) ? FINF : (RLO + (float)(x1 + 1) * CELLW) - qp.x;
    float by0 = (y0 == 0)        ? FINF : qp.y - (RLO + (float)y0 * CELLW);
    float by1 = (y1 == GRID - 1) ? FINF : (RLO + (float)(y1 + 1) * CELLW) - qp.y;
    float b = fminf(fminf(bx0, bx1), fminf(by0, by1));

    // Fallback: ring expansion r >= 2. The branch and every iteration's stop
    // test use the GROUP-combined m (identical across the 4 lanes), so control
    // flow is group-uniform and the masked shfl combine per ring is legal.
    // Each ring: 4-way parallel scan, then group combine -> prompt termination.
    if (b * b < m) {
        for (int r = 2; r < GRID; r++) {
            float lb = (float)(r - 1) * CELLW;
            if (lb * lb >= m) break;
            int xa = max(ix - r, 0), xb = min(ix + r, GRID - 1);
            if (iy - r >= 0)
                scan_cells((iy - r) * GRID + xa, (iy - r) * GRID + xb, sub, qp.x, qp.y, m);
            if (iy + r <= GRID - 1)
                scan_cells((iy + r) * GRID + xa, (iy + r) * GRID + xb, sub, qp.x, qp.y, m);
            int ya = max(iy - r + 1, 0), yb = min(iy + r - 1, GRID - 1);
            if (ix - r >= 0)
                for (int yy = ya; yy <= yb; yy++)
                    scan_cells(yy * GRID + (ix - r), yy * GRID + (ix - r), sub, qp.x, qp.y, m);
            if (ix + r <= GRID - 1)
                for (int yy = ya; yy <= yb; yy++)
                    scan_cells(yy * GRID + (ix + r), yy * GRID + (ix + r), sub, qp.x, qp.y, m);
            m = group_combine(m, gmask);   // group-uniform region
        }
    }
    m = lane_combine(m);   // unconditional; idempotent for fast-path groups

    red[tid] = (sub == 0) ? sqrtf(m) : 0.0f;
    __syncthreads();
    for (int w = QTHREADS / 2; w > 0; w >>= 1) {
        if (tid < w) red[tid] += red[tid + w];
        __syncthreads();
    }
    if (tid == 0) g_bsum[blockIdx.x] = red[0];

    // Done-counter tail: last block computes the mean (fixed order -> determ.)
    __threadfence();
    __syncthreads();
    if (tid == 0) {
        unsigned int prev = atomicAdd(&g_done, 1u);
        s_last = (prev == (unsigned int)(QBLOCKS - 1)) ? 1u : 0u;
    }
    __syncthreads();
    if (s_last) {
        __threadfence();
        float s = 0.0f;
#pragma unroll
        for (int k = 0; k < QBLOCKS / QTHREADS; k++) {
            s += __ldcg(&g_bsum[tid + k * QTHREADS]);
        }
        red[tid] = s;
        __syncthreads();
        for (int w = QTHREADS / 2; w > 0; w >>= 1) {
            if (tid < w) red[tid] += red[tid + w];
            __syncthreads();
        }
        if (tid == 0) {
            out[0] = red[0] * (1.0f / (float)N1);
            g_done = 0;   // reset for next replay
        }
    }
}

extern "C" void kernel_launch(void* const* d_in, const int* in_sizes, int n_in,
                              void* d_out, int out_size) {
    const float2* pos1 = (const float2*)d_in[0];
    const float2* pos2 = (const float2*)d_in[1];
    float* out = (float*)d_out;

    count_kernel<<<N2 / 256, 256>>>(pos2);
    scan_kernel<<<1, 1024>>>();
    scatter_kernel<<<N2 / 256, 256>>>(pos2);
    query_kernel<<<QBLOCKS, QTHREADS>>>(pos1, out);
}

// round 14
// speedup vs baseline: 3.7570x; 1.2909x over previous
#include <cuda_runtime.h>
#include <cstdint>

#define N1 16384
#define N2 16384
#define GRID 128
#define NCELL (GRID * GRID)
#define RLO (-6.0f)
#define RANGE 12.0f
#define CELLW (RANGE / (float)GRID)      // 0.09375, exact in fp32
#define INVCELL ((float)GRID / RANGE)
#define QBLOCKS 512
#define QTHREADS 128
#define GSZ 4                            // lanes per query
#define FINF __uint_as_float(0x7f800000u)

// Cell counts: zero at kernel entry (static zero init; scan_kernel re-zeroes
// after consuming -> replay invariant).
__device__ int g_cnt[NCELL];
// After scan: exclusive prefix. After scatter: inclusive end per cell.
// start(c) = (c>0) ? g_ofs[c-1] : 0.  Rewritten fresh every launch.
__device__ int g_ofs[NCELL];
__device__ float2 g_spts[N2];
__device__ float g_bsum[QBLOCKS];
__device__ unsigned int g_done = 0;

__device__ __forceinline__ int clampi(int v, int lo, int hi) {
    return max(lo, min(hi, v));
}

__device__ __forceinline__ int cell_of(float x, float y) {
    int ix = clampi((int)((x - RLO) * INVCELL), 0, GRID - 1);
    int iy = clampi((int)((y - RLO) * INVCELL), 0, GRID - 1);
    return iy * GRID + ix;
}

// ── Kernel 1: count ──────────────────────────────────────────────────────────
__global__ __launch_bounds__(256)
void count_kernel(const float2* __restrict__ pos2) {
    int i = blockIdx.x * 256 + threadIdx.x;
    float2 p = pos2[i];
    atomicAdd(&g_cnt[cell_of(p.x, p.y)], 1);
}

// ── Kernel 2: exclusive scan over 16384 cells (1 block, int4-vectorized) ─────
__global__ __launch_bounds__(1024)
void scan_kernel() {
    __shared__ int sc[1024];
    const int t = threadIdx.x;
    const int4* cv = (const int4*)&g_cnt[t * 16];
    int4 c[4];
    int loc[16];
    int s = 0;
#pragma unroll
    for (int k = 0; k < 4; k++) c[k] = cv[k];
#pragma unroll
    for (int k = 0; k < 4; k++) {
        loc[4 * k + 0] = s; s += c[k].x;
        loc[4 * k + 1] = s; s += c[k].y;
        loc[4 * k + 2] = s; s += c[k].z;
        loc[4 * k + 3] = s; s += c[k].w;
    }
    sc[t] = s;
    __syncthreads();
    for (int off = 1; off < 1024; off <<= 1) {
        int v = (t >= off) ? sc[t - off] : 0;
        __syncthreads();
        sc[t] += v;
        __syncthreads();
    }
    int excl = sc[t] - s;
    int4* ov = (int4*)&g_ofs[t * 16];
    int4* zv = (int4*)&g_cnt[t * 16];
    const int4 zero = make_int4(0, 0, 0, 0);
#pragma unroll
    for (int k = 0; k < 4; k++) {
        ov[k] = make_int4(excl + loc[4 * k + 0], excl + loc[4 * k + 1],
                          excl + loc[4 * k + 2], excl + loc[4 * k + 3]);
        zv[k] = zero;                    // restore zero invariant for replay
    }
}

// ── Kernel 3: scatter (atomicAdd turns g_ofs into inclusive ends) ────────────
__global__ __launch_bounds__(256)
void scatter_kernel(const float2* __restrict__ pos2) {
    int i = blockIdx.x * 256 + threadIdx.x;
    float2 p = pos2[i];
    int c = cell_of(p.x, p.y);
    int pos = atomicAdd(&g_ofs[c], 1);
    g_spts[pos] = p;
}

// Scan points [s,e) with this lane's stride-GSZ subset. No collective ops.
__device__ __forceinline__ void scan_pts_strided(int s, int e, int sub,
                                                 float qx, float qy, float& m) {
    for (int i = s + sub; i < e; i += GSZ) {
        float2 p = g_spts[i];
        float dx = qx - p.x;
        float dy = qy - p.y;
        m = fminf(m, fmaf(dx, dx, dy * dy));
    }
}

// Scan ALL points in [s,e) (used when rows are distributed across lanes).
__device__ __forceinline__ void scan_pts_all(int s, int e,
                                             float qx, float qy, float& m) {
    for (int i = s; i < e; i++) {
        float2 p = g_spts[i];
        float dx = qx - p.x;
        float dy = qy - p.y;
        m = fminf(m, fmaf(dx, dx, dy * dy));
    }
}

// Full-warp variant: all 32 lanes execute (call sites unconditional).
__device__ __forceinline__ float lane_combine(float m) {
    m = fminf(m, __shfl_xor_sync(0xffffffffu, m, 1));
    m = fminf(m, __shfl_xor_sync(0xffffffffu, m, 2));
    return m;
}

// Group-masked variant: legal inside a branch that is UNIFORM within the
// 4-lane group (all lanes named by gmask execute the same call).
__device__ __forceinline__ float group_combine(float m, unsigned int gmask) {
    m = fminf(m, __shfl_xor_sync(gmask, m, 1));
    m = fminf(m, __shfl_xor_sync(gmask, m, 2));
    return m;
}

// ── Kernel 4: query, GSZ lanes per pos1 point + fused mean ───────────────────
__global__ __launch_bounds__(QTHREADS)
void query_kernel(const float2* __restrict__ pos1, float* __restrict__ out) {
    __shared__ float red[QTHREADS];
    __shared__ unsigned int s_last;
    const int tid  = threadIdx.x;
    const int gtid = blockIdx.x * QTHREADS + tid;
    const int q    = gtid >> 2;
    const int sub  = gtid & (GSZ - 1);
    const unsigned int gmask = 0xFu << (tid & 28);   // this group's 4 lanes

    float2 qp = pos1[q];
    int ix = clampi((int)((qp.x - RLO) * INVCELL), 0, GRID - 1);
    int iy = clampi((int)((qp.y - RLO) * INVCELL), 0, GRID - 1);

    float m = FINF;

    // Fast path: 3x3 neighborhood; 6 range offsets loaded up front (batched).
    int x0 = max(ix - 1, 0), x1 = min(ix + 1, GRID - 1);
    int y0 = max(iy - 1, 0), y1 = min(iy + 1, GRID - 1);
    int nrows = y1 - y0 + 1;
    int rs[3], re[3];
#pragma unroll
    for (int k = 0; k < 3; k++) {
        int yy = min(y0 + k, y1);
        int c0 = yy * GRID + x0;
        rs[k] = (c0 > 0) ? g_ofs[c0 - 1] : 0;
        re[k] = g_ofs[yy * GRID + x1];
    }
#pragma unroll
    for (int k = 0; k < 3; k++) {
        if (k < nrows) scan_pts_strided(rs[k], re[k], sub, qp.x, qp.y, m);
    }

    m = lane_combine(m);   // unconditional: all 32 lanes participate

    // Exact bound for the scanned rect (domain-border sides -> inf).
    float bx0 = (x0 == 0)        ? FINF : qp.x - (RLO + (float)x0 * CELLW);
    float bx1 = (x1 == GRID - 1) ? FINF : (RLO + (float)(x1 + 1) * CELLW) - qp.x;
    float by0 = (y0 == 0)        ? FINF : qp.y - (RLO + (float)y0 * CELLW);
    float by1 = (y1 == GRID - 1) ? FINF : (RLO + (float)(y1 + 1) * CELLW) - qp.y;
    float b = fminf(fminf(bx0, bx1), fminf(by0, by1));

    // Fallback (rare, outer queries): geometrically-doubling square re-scans.
    // Each square: rows distributed across the 4 lanes (whole contiguous row
    // ranges -> 2 ofs loads per row, near-empty cells). Control flow depends
    // only on the GROUP-combined m and R -> group-uniform, masked shfl legal.
    // R doubles to 128, which covers the grid (bound -> inf) => guaranteed exit.
    if (b * b < m) {
        for (int R = 2; R <= GRID; R <<= 1) {
            int xa = max(ix - R, 0), xb = min(ix + R, GRID - 1);
            int ya = max(iy - R, 0), yb = min(iy + R, GRID - 1);
            for (int yy = ya + sub; yy <= yb; yy += GSZ) {
                int c0 = yy * GRID + xa;
                int s = (c0 > 0) ? g_ofs[c0 - 1] : 0;
                int e = g_ofs[yy * GRID + xb];
                scan_pts_all(s, e, qp.x, qp.y, m);
            }
            m = group_combine(m, gmask);   // group-uniform region
            float sx0 = (xa == 0)        ? FINF : qp.x - (RLO + (float)xa * CELLW);
            float sx1 = (xb == GRID - 1) ? FINF : (RLO + (float)(xb + 1) * CELLW) - qp.x;
            float sy0 = (ya == 0)        ? FINF : qp.y - (RLO + (float)ya * CELLW);
            float sy1 = (yb == GRID - 1) ? FINF : (RLO + (float)(yb + 1) * CELLW) - qp.y;
            float sb = fminf(fminf(sx0, sx1), fminf(sy0, sy1));
            if (sb * sb >= m) break;
        }
    }
    m = lane_combine(m);   // unconditional; idempotent for fast-path groups

    red[tid] = (sub == 0) ? sqrtf(m) : 0.0f;
    __syncthreads();
    for (int w = QTHREADS / 2; w > 0; w >>= 1) {
        if (tid < w) red[tid] += red[tid + w];
        __syncthreads();
    }
    if (tid == 0) g_bsum[blockIdx.x] = red[0];

    // Done-counter tail: last block computes the mean (fixed order -> determ.)
    __threadfence();
    __syncthreads();
    if (tid == 0) {
        unsigned int prev = atomicAdd(&g_done, 1u);
        s_last = (prev == (unsigned int)(QBLOCKS - 1)) ? 1u : 0u;
    }
    __syncthreads();
    if (s_last) {
        __threadfence();
        float s = 0.0f;
#pragma unroll
        for (int k = 0; k < QBLOCKS / QTHREADS; k++) {
            s += __ldcg(&g_bsum[tid + k * QTHREADS]);
        }
        red[tid] = s;
        __syncthreads();
        for (int w = QTHREADS / 2; w > 0; w >>= 1) {
            if (tid < w) red[tid] += red[tid + w];
            __syncthreads();
        }
        if (tid == 0) {
            out[0] = red[0] * (1.0f / (float)N1);
            g_done = 0;   // reset for next replay
        }
    }
}

extern "C" void kernel_launch(void* const* d_in, const int* in_sizes, int n_in,
                              void* d_out, int out_size) {
    const float2* pos1 = (const float2*)d_in[0];
    const float2* pos2 = (const float2*)d_in[1];
    float* out = (float*)d_out;

    count_kernel<<<N2 / 256, 256>>>(pos2);
    scan_kernel<<<1, 1024>>>();
    scatter_kernel<<<N2 / 256, 256>>>(pos2);
    query_kernel<<<QBLOCKS, QTHREADS>>>(pos1, out);
}